// round 4
// baseline (speedup 1.0000x reference)
#include <cuda_runtime.h>
#include <math.h>
#include <stdint.h>

#define BB   2
#define NQ   1024
#define NKK  2048
#define DIMN 1024
#define NH   16
#define HDIM 64

// ---------------- scratch (static device globals: no runtime allocation) ----
__device__ float g_qp[(size_t)BB * NH * NQ * HDIM];    // (B,H,NQ,HD)   8 MiB
__device__ float g_kp[(size_t)BB * NH * NKK * HDIM];   // (B,H,NK,HD)  16 MiB
__device__ float g_vp[(size_t)BB * NH * NKK * HDIM];   // (B,H,NK,HD)  16 MiB
__device__ float g_att[(size_t)BB * NQ * NH * HDIM];   // (B,NQ,H*HD)   8 MiB
__device__ float g_part[BB * 256];
__device__ float g_coef[BB];
__device__ int   g_mask_mode;   // 0=uint8, 1=float32, 2=int32

// ---------------- mask dtype detection -------------------------------------
__global__ void detect_kernel(const unsigned int* __restrict__ w) {
    __shared__ int hasF, le1;
    if (threadIdx.x == 0) { hasF = 0; le1 = 1; }
    __syncthreads();
    unsigned v = w[threadIdx.x];
    if (v == 0x3F800000u) atomicExch(&hasF, 1);
    if (v > 1u)           atomicExch(&le1, 0);
    __syncthreads();
    if (threadIdx.x == 0) g_mask_mode = hasF ? 1 : (le1 ? 2 : 0);
}

__device__ __forceinline__ bool mget(const void* p, size_t i, int mode) {
    if (mode == 1) return ((const float*)p)[i] != 0.0f;
    if (mode == 2) return ((const int*)p)[i] != 0;
    return ((const unsigned char*)p)[i] != 0;
}

// ---------------- SGEMM: C = A(MxK) @ W(NxK)^T, K=N=1024 -------------------
// dsel: 0 -> g_qp, 1 -> g_kp, 2 -> g_vp  (scatter to (B,H,N,HD) layout)
//       3 -> Cout (final output, row-masked by key_padding_mask_q)
__global__ void __launch_bounds__(256) sgemm_nt(
    const float* __restrict__ Ain, const float* __restrict__ Bw,
    float* __restrict__ Cout, int M, int Nseq, int dsel,
    const void* __restrict__ kpmq)
{
    __shared__ float As[8][128];
    __shared__ float Bs[8][128];

    const float* A = (dsel == 3) ? g_att : Ain;

    int tid = threadIdx.x;
    int tx = tid & 15, ty = tid >> 4;
    int row0 = blockIdx.y * 128, col0 = blockIdx.x * 128;

    int lr = tid >> 1;        // 0..127
    int lc = (tid & 1) * 4;   // 0 or 4

    const float* Ag = A  + (size_t)(row0 + lr) * DIMN + lc;
    const float* Bg = Bw + (size_t)(col0 + lr) * DIMN + lc;

    float acc[8][8];
#pragma unroll
    for (int i = 0; i < 8; i++)
#pragma unroll
        for (int j = 0; j < 8; j++) acc[i][j] = 0.0f;

    for (int k0 = 0; k0 < DIMN; k0 += 8) {
        float4 a4 = *(const float4*)(Ag);
        float4 b4 = *(const float4*)(Bg);
        Ag += 8; Bg += 8;
        As[lc + 0][lr] = a4.x; As[lc + 1][lr] = a4.y;
        As[lc + 2][lr] = a4.z; As[lc + 3][lr] = a4.w;
        Bs[lc + 0][lr] = b4.x; Bs[lc + 1][lr] = b4.y;
        Bs[lc + 2][lr] = b4.z; Bs[lc + 3][lr] = b4.w;
        __syncthreads();
#pragma unroll
        for (int kk = 0; kk < 8; kk++) {
            float ra[8], rb[8];
            *(float4*)(&ra[0]) = *(const float4*)(&As[kk][ty * 4]);
            *(float4*)(&ra[4]) = *(const float4*)(&As[kk][64 + ty * 4]);
            *(float4*)(&rb[0]) = *(const float4*)(&Bs[kk][tx * 4]);
            *(float4*)(&rb[4]) = *(const float4*)(&Bs[kk][64 + tx * 4]);
#pragma unroll
            for (int i = 0; i < 8; i++)
#pragma unroll
                for (int j = 0; j < 8; j++)
                    acc[i][j] = fmaf(ra[i], rb[j], acc[i][j]);
        }
        __syncthreads();
    }

    int mode = g_mask_mode;
#pragma unroll
    for (int i = 0; i < 8; i++) {
        int r = (i < 4) ? (ty * 4 + i) : (64 + ty * 4 + i - 4);
        int m = row0 + r;
        float rowscale = 1.0f;
        if (dsel == 3) rowscale = mget(kpmq, (size_t)m, mode) ? 1.0f : 0.0f;
#pragma unroll
        for (int j = 0; j < 8; j++) {
            int c = (j < 4) ? (tx * 4 + j) : (64 + tx * 4 + j - 4);
            int n = col0 + c;
            if (dsel == 3) {
                Cout[(size_t)m * DIMN + n] = acc[i][j] * rowscale;
            } else {
                float* dst = (dsel == 0) ? g_qp : ((dsel == 1) ? g_kp : g_vp);
                int bb = m / Nseq, ns = m - bb * Nseq;
                int hh = n >> 6, hd = n & 63;
                dst[(((size_t)bb * NH + hh) * Nseq + ns) * HDIM + hd] = acc[i][j];
            }
        }
    }
}

// ---------------- distance mean -> gate coefficient -------------------------
__global__ void mean_stage1(const float* __restrict__ dist,
                            const void* __restrict__ am,
                            const void* __restrict__ kpmk)
{
    int mode = g_mask_mode;
    int b = blockIdx.y;
    size_t base = (size_t)b * NQ * NKK;
    float s = 0.0f;
    for (int i = blockIdx.x * 256 + threadIdx.x; i < NQ * NKK; i += 256 * 256) {
        int kk = i & (NKK - 1);
        if (mget(am, base + i, mode) && mget(kpmk, (size_t)b * NKK + kk, mode))
            s += dist[base + i];
    }
    __shared__ float red[256];
    red[threadIdx.x] = s;
    __syncthreads();
    for (int st = 128; st > 0; st >>= 1) {
        if (threadIdx.x < st) red[threadIdx.x] += red[threadIdx.x + st];
        __syncthreads();
    }
    if (threadIdx.x == 0) g_part[b * 256 + blockIdx.x] = red[0];
}

__global__ void mean_stage2(const float* __restrict__ galpha)
{
    int b = blockIdx.x;
    __shared__ float red[256];
    red[threadIdx.x] = g_part[b * 256 + threadIdx.x];
    __syncthreads();
    for (int st = 128; st > 0; st >>= 1) {
        if (threadIdx.x < st) red[threadIdx.x] += red[threadIdx.x + st];
        __syncthreads();
    }
    if (threadIdx.x == 0) {
        float mean = red[0] / ((float)NQ * (float)NKK + 1e-6f);
        mean = fmaxf(mean, 1e-6f);
        float a = galpha[0];
        float alpha = log1pf(__expf(a));   // softplus
        g_coef[b] = alpha / mean;
    }
}

// ---------------- fused flash attention with distance gating ----------------
__device__ __forceinline__ float redmax16(float v) {
    v = fmaxf(v, __shfl_xor_sync(0xffffffffu, v, 1));
    v = fmaxf(v, __shfl_xor_sync(0xffffffffu, v, 2));
    v = fmaxf(v, __shfl_xor_sync(0xffffffffu, v, 4));
    v = fmaxf(v, __shfl_xor_sync(0xffffffffu, v, 8));
    return v;
}
__device__ __forceinline__ float redsum16(float v) {
    v += __shfl_xor_sync(0xffffffffu, v, 1);
    v += __shfl_xor_sync(0xffffffffu, v, 2);
    v += __shfl_xor_sync(0xffffffffu, v, 4);
    v += __shfl_xor_sync(0xffffffffu, v, 8);
    return v;
}

#define ATTN_SMEM_FLOATS (2 * 64 * 65 + 64 * 64)

__global__ void __launch_bounds__(256) attn_kernel(
    const float* __restrict__ dist, const void* __restrict__ amask,
    const void* __restrict__ kpmk)
{
    extern __shared__ float sm[];
    float* Qt  = sm;                 // [d][q]  64x65 (transposed, padded)
    float* KtP = sm + 64 * 65;       // [d][k] for S phase, then P as [k][q]
    float* Vs  = sm + 2 * 64 * 65;   // [k][hd] 64x64

    int tid = threadIdx.x;
    int tx = tid & 15, ty = tid >> 4;
    int q0 = blockIdx.x * 64;
    int h = blockIdx.y, b = blockIdx.z;
    int mode = g_mask_mode;
    float coef = g_coef[b];

    // load Q tile transposed: Qt[d][q]
    const float* Qg = g_qp + ((size_t)(b * NH + h) * NQ + q0) * HDIM;
#pragma unroll
    for (int l = 0; l < 16; l++) {
        int idx = tid + l * 256;
        int qq = idx >> 6, d = idx & 63;
        Qt[d * 65 + qq] = Qg[idx];
    }

    float m_i[4], Z[4], Zg[4], O[4][4];
#pragma unroll
    for (int i = 0; i < 4; i++) {
        m_i[i] = -1e30f; Z[i] = 0.0f; Zg[i] = 0.0f;
#pragma unroll
        for (int j = 0; j < 4; j++) O[i][j] = 0.0f;
    }

    for (int k0 = 0; k0 < NKK; k0 += 64) {
        __syncthreads();  // previous-tile PV reads done (also covers Qt store, 1st iter)
        const float* Kg = g_kp + ((size_t)(b * NH + h) * NKK + k0) * HDIM;
        const float* Vg = g_vp + ((size_t)(b * NH + h) * NKK + k0) * HDIM;
#pragma unroll
        for (int l = 0; l < 16; l++) {
            int idx = tid + l * 256;
            int kk = idx >> 6, d = idx & 63;
            KtP[d * 65 + kk] = Kg[idx];
            Vs[idx] = Vg[idx];
        }
        __syncthreads();

        // S = Q K^T
        float acc[4][4];
#pragma unroll
        for (int i = 0; i < 4; i++)
#pragma unroll
            for (int j = 0; j < 4; j++) acc[i][j] = 0.0f;
#pragma unroll 8
        for (int d = 0; d < 64; d++) {
            float ra[4], rb[4];
#pragma unroll
            for (int i = 0; i < 4; i++) ra[i] = Qt[d * 65 + ty * 4 + i];
#pragma unroll
            for (int j = 0; j < 4; j++) rb[j] = KtP[d * 65 + tx * 4 + j];
#pragma unroll
            for (int i = 0; i < 4; i++)
#pragma unroll
                for (int j = 0; j < 4; j++)
                    acc[i][j] = fmaf(ra[i], rb[j], acc[i][j]);
        }

        bool kval[4];
#pragma unroll
        for (int j = 0; j < 4; j++)
            kval[j] = mget(kpmk, (size_t)b * NKK + k0 + tx * 4 + j, mode);

        __syncthreads();  // done reading KtP (K^T); safe to overwrite with P

        // masked online softmax + gate; write P = e*g into KtP as [k][q]
#pragma unroll
        for (int i = 0; i < 4; i++) {
            int qg = q0 + ty * 4 + i;
            size_t rbase = ((size_t)b * NQ + qg) * NKK + k0;
            float s[4];
            float mt = -3.0e38f;
#pragma unroll
            for (int j = 0; j < 4; j++) {
                int kg = tx * 4 + j;
                bool vv = kval[j] && mget(amask, rbase + kg, mode);
                s[j] = vv ? acc[i][j] * 0.125f : -3.0e38f;
                mt = fmaxf(mt, s[j]);
            }
            mt = redmax16(mt);
            float mn = fmaxf(m_i[i], mt);
            float c = __expf(m_i[i] - mn);
            m_i[i] = mn;
            float zl = 0.0f, zgl = 0.0f;
#pragma unroll
            for (int j = 0; j < 4; j++) {
                float e  = __expf(s[j] - mn);      // 0 for invalid (underflow)
                float dv = dist[rbase + tx * 4 + j];
                float g  = __expf(-coef * dv);
                float p  = e * g;
                zl  += e;
                zgl += p;
                KtP[(tx * 4 + j) * 65 + ty * 4 + i] = p;
            }
            Z[i]  = Z[i]  * c + zl;
            Zg[i] = Zg[i] * c + zgl;
#pragma unroll
            for (int j = 0; j < 4; j++) O[i][j] *= c;
        }
        __syncthreads();

        // O += P @ V
#pragma unroll 8
        for (int kk = 0; kk < 64; kk++) {
            float pa[4], vb[4];
#pragma unroll
            for (int i = 0; i < 4; i++) pa[i] = KtP[kk * 65 + ty * 4 + i];
#pragma unroll
            for (int j = 0; j < 4; j++) vb[j] = Vs[kk * 64 + tx * 4 + j];
#pragma unroll
            for (int i = 0; i < 4; i++)
#pragma unroll
                for (int j = 0; j < 4; j++)
                    O[i][j] = fmaf(pa[i], vb[j], O[i][j]);
        }
    }

    // epilogue: out = O / (Zg + 1e-6 * Z), scattered to (B,NQ,H*HD)
#pragma unroll
    for (int i = 0; i < 4; i++) {
        float Zt  = redsum16(Z[i]);
        float Zgt = redsum16(Zg[i]);
        float inv = 1.0f / (Zgt + 1e-6f * Zt + 1e-30f);
        int qg = q0 + ty * 4 + i;
        float* outp = g_att + ((size_t)(b * NQ + qg) * NH + h) * HDIM;
#pragma unroll
        for (int j = 0; j < 4; j++)
            outp[tx * 4 + j] = O[i][j] * inv;
    }
}

// ---------------- launch -----------------------------------------------------
extern "C" void kernel_launch(void* const* d_in, const int* in_sizes, int n_in,
                              void* d_out, int out_size)
{
    const float* q     = (const float*)d_in[0];
    const float* k     = (const float*)d_in[1];
    const float* v     = (const float*)d_in[2];
    const float* dist  = (const float*)d_in[3];
    const void*  amask = d_in[4];
    const void*  kpmq  = d_in[5];
    const void*  kpmk  = d_in[6];
    const float* Wq    = (const float*)d_in[7];
    const float* Wk    = (const float*)d_in[8];
    const float* Wv    = (const float*)d_in[9];
    const float* Wo    = (const float*)d_in[10];
    const float* ga    = (const float*)d_in[11];
    float* out = (float*)d_out;

    const int attn_smem = ATTN_SMEM_FLOATS * (int)sizeof(float);  // 49664
    cudaFuncSetAttribute(attn_kernel,
                         cudaFuncAttributeMaxDynamicSharedMemorySize, attn_smem);

    detect_kernel<<<1, 256>>>((const unsigned int*)amask);

    sgemm_nt<<<dim3(8, 16), 256>>>(q, Wq, nullptr, BB * NQ,  NQ,  0, nullptr);
    sgemm_nt<<<dim3(8, 32), 256>>>(k, Wk, nullptr, BB * NKK, NKK, 1, nullptr);
    sgemm_nt<<<dim3(8, 32), 256>>>(v, Wv, nullptr, BB * NKK, NKK, 2, nullptr);

    mean_stage1<<<dim3(256, BB), 256>>>(dist, amask, kpmk);
    mean_stage2<<<BB, 256>>>(ga);

    attn_kernel<<<dim3(NQ / 64, NH, BB), 256, attn_smem>>>(dist, amask, kpmk);

    sgemm_nt<<<dim3(8, 16), 256>>>(nullptr, Wo, out, BB * NQ, NQ, 3, kpmq);
}

// round 5
// speedup vs baseline: 2.4352x; 2.4352x over previous
#include <cuda_runtime.h>
#include <math.h>
#include <stdint.h>

#define BB   2
#define NQ   1024
#define NKK  2048
#define DIMN 1024
#define NH   16
#define HDIM 64

// ---------------- scratch (static device globals) ---------------------------
__device__ float g_qp[(size_t)BB * NH * NQ * HDIM];    // (B,H,NQ,HD), pre-scaled by 0.125
__device__ float g_kp[(size_t)BB * NH * NKK * HDIM];   // (B,H,NK,HD)
__device__ float g_vp[(size_t)BB * NH * NKK * HDIM];   // (B,H,NK,HD)
__device__ float g_att[(size_t)BB * NQ * NH * HDIM];   // (B,NQ,H*HD)
__device__ float g_gate[(size_t)BB * NQ * NKK];        // gate*valid, 0 if masked (67MB)
__device__ float g_part[BB * 256];
__device__ float g_coef[BB];
__device__ int   g_mask_mode;   // 0=uint8, 1=float32, 2=int32

// ---------------- mask dtype detection -------------------------------------
__global__ void detect_kernel(const unsigned int* __restrict__ w) {
    __shared__ int hasF, le1;
    if (threadIdx.x == 0) { hasF = 0; le1 = 1; }
    __syncthreads();
    unsigned v = w[threadIdx.x];
    if (v == 0x3F800000u) atomicExch(&hasF, 1);
    if (v > 1u)           atomicExch(&le1, 0);
    __syncthreads();
    if (threadIdx.x == 0) g_mask_mode = hasF ? 1 : (le1 ? 2 : 0);
}

__device__ __forceinline__ bool mget(const void* p, size_t i, int mode) {
    if (mode == 1) return ((const float*)p)[i] != 0.0f;
    if (mode == 2) return ((const int*)p)[i] != 0;
    return ((const unsigned char*)p)[i] != 0;
}

// ---------------- tf32 helpers ----------------------------------------------
__device__ __forceinline__ unsigned f2tf(float f) {
    unsigned u;
    asm("cvt.rna.tf32.f32 %0, %1;" : "=r"(u) : "f"(f));
    return u;
}

__device__ __forceinline__ void mma_tf32(float* d, const unsigned* a, const unsigned* b) {
    asm volatile(
        "mma.sync.aligned.m16n8k8.row.col.f32.tf32.tf32.f32 "
        "{%0,%1,%2,%3}, {%4,%5,%6,%7}, {%8,%9}, {%0,%1,%2,%3};"
        : "+f"(d[0]), "+f"(d[1]), "+f"(d[2]), "+f"(d[3])
        : "r"(a[0]), "r"(a[1]), "r"(a[2]), "r"(a[3]), "r"(b[0]), "r"(b[1]));
}

// ---------------- TF32 GEMM: C = A(MxK) @ W(NxK)^T, K=1024 ------------------
// dsel: 0 -> g_qp (scaled 0.125), 1 -> g_kp, 2 -> g_vp, 3 -> Cout (row-masked)
__global__ void __launch_bounds__(256, 2) gemm_tf32(
    const float* __restrict__ Ain, const float* __restrict__ Bw,
    float* __restrict__ Cout, int M, int Nseq, int dsel,
    const void* __restrict__ kpmq)
{
    __shared__ unsigned As[128][36];
    __shared__ unsigned Bs[128][36];

    const float* A = (dsel == 3) ? g_att : Ain;

    int tid  = threadIdx.x;
    int lane = tid & 31;
    int warp = tid >> 5;
    int g    = lane >> 2;
    int t4   = lane & 3;
    int wm   = warp >> 2;       // 0..1
    int wn   = warp & 3;        // 0..3
    int row0 = blockIdx.y * 128, col0 = blockIdx.x * 128;

    int lrow = tid >> 1;               // 0..127
    int lc16 = (tid & 1) * 16;         // 0 or 16

    const float* Ag = A  + (size_t)(row0 + lrow) * DIMN + lc16;
    const float* Bg = Bw + (size_t)(col0 + lrow) * DIMN + lc16;

    float acc[4][4][4];
#pragma unroll
    for (int i = 0; i < 4; i++)
#pragma unroll
        for (int j = 0; j < 4; j++)
#pragma unroll
            for (int c = 0; c < 4; c++) acc[i][j][c] = 0.0f;

    for (int k0 = 0; k0 < DIMN; k0 += 32) {
        __syncthreads();
#pragma unroll
        for (int i = 0; i < 4; i++) {
            float4 a4 = *(const float4*)(Ag + k0 + i * 4);
            float4 b4 = *(const float4*)(Bg + k0 + i * 4);
            uint4 au = make_uint4(f2tf(a4.x), f2tf(a4.y), f2tf(a4.z), f2tf(a4.w));
            uint4 bu = make_uint4(f2tf(b4.x), f2tf(b4.y), f2tf(b4.z), f2tf(b4.w));
            *(uint4*)(&As[lrow][lc16 + i * 4]) = au;
            *(uint4*)(&Bs[lrow][lc16 + i * 4]) = bu;
        }
        __syncthreads();

#pragma unroll
        for (int kk = 0; kk < 4; kk++) {
            int kb = kk * 8;
            unsigned afr[4][4];
#pragma unroll
            for (int mi = 0; mi < 4; mi++) {
                int Rb = wm * 64 + mi * 16;
                afr[mi][0] = As[Rb + g][kb + t4];
                afr[mi][1] = As[Rb + g + 8][kb + t4];
                afr[mi][2] = As[Rb + g][kb + t4 + 4];
                afr[mi][3] = As[Rb + g + 8][kb + t4 + 4];
            }
#pragma unroll
            for (int nj = 0; nj < 4; nj++) {
                int Cb = wn * 32 + nj * 8;
                unsigned bfr[2];
                bfr[0] = Bs[Cb + g][kb + t4];
                bfr[1] = Bs[Cb + g][kb + t4 + 4];
#pragma unroll
                for (int mi = 0; mi < 4; mi++)
                    mma_tf32(acc[mi][nj], afr[mi], bfr);
            }
        }
    }

    int mode = g_mask_mode;
#pragma unroll
    for (int mi = 0; mi < 4; mi++) {
#pragma unroll
        for (int h2 = 0; h2 < 2; h2++) {
            int r = row0 + wm * 64 + mi * 16 + g + 8 * h2;
            float rowscale = 1.0f;
            if (dsel == 3) rowscale = mget(kpmq, (size_t)r, mode) ? 1.0f : 0.0f;
#pragma unroll
            for (int nj = 0; nj < 4; nj++) {
                int c = col0 + wn * 32 + nj * 8 + 2 * t4;
                float v0 = acc[mi][nj][2 * h2];
                float v1 = acc[mi][nj][2 * h2 + 1];
                if (dsel == 0) { v0 *= 0.125f; v1 *= 0.125f; }
                if (dsel == 3) {
                    Cout[(size_t)r * DIMN + c]     = v0 * rowscale;
                    Cout[(size_t)r * DIMN + c + 1] = v1 * rowscale;
                } else {
                    float* dst = (dsel == 0) ? g_qp : ((dsel == 1) ? g_kp : g_vp);
                    int bb = r / Nseq, ns = r - bb * Nseq;
                    int hh = c >> 6, hd = c & 63;
                    float* dp = dst + (((size_t)bb * NH + hh) * Nseq + ns) * HDIM + hd;
                    dp[0] = v0; dp[1] = v1;
                }
            }
        }
    }
}

// ---------------- distance mean -> gate coefficient -------------------------
__global__ void mean_stage1(const float* __restrict__ dist,
                            const void* __restrict__ am,
                            const void* __restrict__ kpmk)
{
    int mode = g_mask_mode;
    int b = blockIdx.y;
    size_t base = (size_t)b * NQ * NKK;
    float s = 0.0f;
    for (int i = blockIdx.x * 256 + threadIdx.x; i < NQ * NKK; i += 256 * 256) {
        int kk = i & (NKK - 1);
        if (mget(am, base + i, mode) && mget(kpmk, (size_t)b * NKK + kk, mode))
            s += dist[base + i];
    }
    __shared__ float red[256];
    red[threadIdx.x] = s;
    __syncthreads();
    for (int st = 128; st > 0; st >>= 1) {
        if (threadIdx.x < st) red[threadIdx.x] += red[threadIdx.x + st];
        __syncthreads();
    }
    if (threadIdx.x == 0) g_part[b * 256 + blockIdx.x] = red[0];
}

__global__ void mean_stage2(const float* __restrict__ galpha)
{
    int b = blockIdx.x;
    __shared__ float red[256];
    red[threadIdx.x] = g_part[b * 256 + threadIdx.x];
    __syncthreads();
    for (int st = 128; st > 0; st >>= 1) {
        if (threadIdx.x < st) red[threadIdx.x] += red[threadIdx.x + st];
        __syncthreads();
    }
    if (threadIdx.x == 0) {
        float mean = red[0] / ((float)NQ * (float)NKK + 1e-6f);
        mean = fmaxf(mean, 1e-6f);
        float a = galpha[0];
        float alpha = log1pf(__expf(a));   // softplus
        g_coef[b] = alpha / mean;
    }
}

// ---------------- precompute gate*valid ------------------------------------
__global__ void gate_kernel(const float* __restrict__ dist,
                            const void* __restrict__ am,
                            const void* __restrict__ kpmk)
{
    int mode = g_mask_mode;
    size_t i0 = ((size_t)blockIdx.x * 256 + threadIdx.x) * 4;
    const size_t per_b = (size_t)NQ * NKK;
#pragma unroll
    for (int u = 0; u < 4; u++) {
        size_t i = i0 + u;
        int b = (int)(i / per_b);
        size_t rem = i - (size_t)b * per_b;
        int kk = (int)(rem & (NKK - 1));
        bool valid = mget(am, i, mode) && mget(kpmk, (size_t)b * NKK + kk, mode);
        g_gate[i] = valid ? __expf(-g_coef[b] * dist[i]) : 0.0f;
    }
}

// ---------------- fused flash attention (tf32 mma) --------------------------
// block: 256 thr = 8 warps; q-tile 128 (warp w owns rows w*16..w*16+15); k-tile 64
#define QS_STRIDE 68
#define KS_STRIDE 68
#define VS_STRIDE 72
#define PS_STRIDE 68
#define ATTN_SMEM_UINTS (128*QS_STRIDE + 64*KS_STRIDE + 64*VS_STRIDE + 128*PS_STRIDE)

__device__ __forceinline__ float qmax(float v) {
    v = fmaxf(v, __shfl_xor_sync(0xffffffffu, v, 1));
    v = fmaxf(v, __shfl_xor_sync(0xffffffffu, v, 2));
    return v;
}
__device__ __forceinline__ float qsum(float v) {
    v += __shfl_xor_sync(0xffffffffu, v, 1);
    v += __shfl_xor_sync(0xffffffffu, v, 2);
    return v;
}

__global__ void __launch_bounds__(256, 1) attn_kernel()
{
    extern __shared__ unsigned smu[];
    unsigned* Qs = smu;                                   // [128][68]
    unsigned* Ks = Qs + 128 * QS_STRIDE;                  // [64][68]
    unsigned* Vs = Ks + 64 * KS_STRIDE;                   // [64][72]
    unsigned* Ps = Vs + 64 * VS_STRIDE;                   // [128][68]

    int tid  = threadIdx.x;
    int lane = tid & 31;
    int warp = tid >> 5;
    int g    = lane >> 2;
    int t4   = lane & 3;
    int R    = warp * 16;             // this warp's q rows within tile

    int q0 = blockIdx.x * 128;
    int h  = blockIdx.y, b = blockIdx.z;

    // load Q tile (128x64) -> Qs, tf32
    {
        const float* Qg = g_qp + ((size_t)(b * NH + h) * NQ + q0) * HDIM;
#pragma unroll
        for (int l = 0; l < 8; l++) {
            int idx4 = tid + l * 256;        // over 2048 float4s
            int row = idx4 >> 4, d4 = (idx4 & 15) * 4;
            float4 v = *(const float4*)(Qg + row * HDIM + d4);
            uint4 u = make_uint4(f2tf(v.x), f2tf(v.y), f2tf(v.z), f2tf(v.w));
            *(uint4*)(&Qs[row * QS_STRIDE + d4]) = u;
        }
    }

    float O[8][4];
    float mrow[2] = {-1e30f, -1e30f}, Z2[2] = {0.f, 0.f}, Zg2[2] = {0.f, 0.f};
#pragma unroll
    for (int nj = 0; nj < 8; nj++)
#pragma unroll
        for (int c = 0; c < 4; c++) O[nj][c] = 0.0f;

    const size_t kv_base = (size_t)(b * NH + h) * NKK * HDIM;

    for (int kbase = 0; kbase < NKK; kbase += 64) {
        __syncthreads();   // all warps done with previous Ks/Vs (and Qs stores, iter 0)
        {
            const float* Kg = g_kp + kv_base + (size_t)kbase * HDIM;
            const float* Vg = g_vp + kv_base + (size_t)kbase * HDIM;
#pragma unroll
            for (int l = 0; l < 4; l++) {
                int idx4 = tid + l * 256;    // over 1024 float4s
                int row = idx4 >> 4, d4 = (idx4 & 15) * 4;
                float4 kv = *(const float4*)(Kg + row * HDIM + d4);
                float4 vv = *(const float4*)(Vg + row * HDIM + d4);
                *(uint4*)(&Ks[row * KS_STRIDE + d4]) =
                    make_uint4(f2tf(kv.x), f2tf(kv.y), f2tf(kv.z), f2tf(kv.w));
                *(uint4*)(&Vs[row * VS_STRIDE + d4]) =
                    make_uint4(f2tf(vv.x), f2tf(vv.y), f2tf(vv.z), f2tf(vv.w));
            }
        }
        __syncthreads();

        // ---- S = Q K^T (128x64 tile; this warp: rows R..R+15) ----
        float sfr[8][4];
#pragma unroll
        for (int nj = 0; nj < 8; nj++)
#pragma unroll
            for (int c = 0; c < 4; c++) sfr[nj][c] = 0.0f;

#pragma unroll
        for (int kk = 0; kk < 8; kk++) {
            int kb = kk * 8;
            unsigned afr[4];
            afr[0] = Qs[(R + g) * QS_STRIDE + kb + t4];
            afr[1] = Qs[(R + g + 8) * QS_STRIDE + kb + t4];
            afr[2] = Qs[(R + g) * QS_STRIDE + kb + t4 + 4];
            afr[3] = Qs[(R + g + 8) * QS_STRIDE + kb + t4 + 4];
#pragma unroll
            for (int nj = 0; nj < 8; nj++) {
                unsigned bfr[2];
                bfr[0] = Ks[(nj * 8 + g) * KS_STRIDE + kb + t4];
                bfr[1] = Ks[(nj * 8 + g) * KS_STRIDE + kb + t4 + 4];
                mma_tf32(sfr[nj], afr, bfr);
            }
        }

        // ---- online softmax + gate, per half-row (rows R+g and R+g+8) ----
#pragma unroll
        for (int hf = 0; hf < 2; hf++) {
            int qrow = q0 + R + g + 8 * hf;
            const float* Gp = g_gate + ((size_t)b * NQ + qrow) * NKK + kbase;
            float Gv[16], sv[16];
            float mt = -3.0e38f;
#pragma unroll
            for (int nj = 0; nj < 8; nj++) {
                float2 gg = *(const float2*)(Gp + nj * 8 + 2 * t4);
                Gv[2 * nj] = gg.x; Gv[2 * nj + 1] = gg.y;
                float s0 = (gg.x > 0.f) ? sfr[nj][2 * hf]     : -3.0e38f;
                float s1 = (gg.y > 0.f) ? sfr[nj][2 * hf + 1] : -3.0e38f;
                sv[2 * nj] = s0; sv[2 * nj + 1] = s1;
                mt = fmaxf(mt, fmaxf(s0, s1));
            }
            mt = qmax(mt);
            float mn = fmaxf(mrow[hf], mt);
            float cs = __expf(mrow[hf] - mn);
            mrow[hf] = mn;
            float zl = 0.f, zgl = 0.f;
#pragma unroll
            for (int nj = 0; nj < 8; nj++) {
                float e0 = __expf(sv[2 * nj] - mn);
                float e1 = __expf(sv[2 * nj + 1] - mn);
                float p0 = e0 * Gv[2 * nj];
                float p1 = e1 * Gv[2 * nj + 1];
                zl += e0 + e1; zgl += p0 + p1;
                uint2 pu = make_uint2(f2tf(p0), f2tf(p1));
                *(uint2*)(&Ps[(R + g + 8 * hf) * PS_STRIDE + nj * 8 + 2 * t4]) = pu;
            }
            Z2[hf]  = Z2[hf]  * cs + zl;
            Zg2[hf] = Zg2[hf] * cs + zgl;
#pragma unroll
            for (int nj = 0; nj < 8; nj++) {
                O[nj][2 * hf]     *= cs;
                O[nj][2 * hf + 1] *= cs;
            }
        }
        __syncwarp();   // P rows are warp-private; order STS -> cross-lane LDS

        // ---- O += P @ V ----
#pragma unroll
        for (int kk = 0; kk < 8; kk++) {
            int kb = kk * 8;
            unsigned afr[4];
            afr[0] = Ps[(R + g) * PS_STRIDE + kb + t4];
            afr[1] = Ps[(R + g + 8) * PS_STRIDE + kb + t4];
            afr[2] = Ps[(R + g) * PS_STRIDE + kb + t4 + 4];
            afr[3] = Ps[(R + g + 8) * PS_STRIDE + kb + t4 + 4];
#pragma unroll
            for (int nj = 0; nj < 8; nj++) {
                unsigned bfr[2];
                bfr[0] = Vs[(kb + t4) * VS_STRIDE + nj * 8 + g];
                bfr[1] = Vs[(kb + t4 + 4) * VS_STRIDE + nj * 8 + g];
                mma_tf32(O[nj], afr, bfr);
            }
        }
    }

    // epilogue: out = O / (Zg + 1e-6 * Z) scattered to (B,NQ,H*HD)
#pragma unroll
    for (int hf = 0; hf < 2; hf++) {
        float Zt  = qsum(Z2[hf]);
        float Zgt = qsum(Zg2[hf]);
        float inv = 1.0f / (Zgt + 1e-6f * Zt + 1e-30f);
        int qrow = q0 + R + g + 8 * hf;
        float* outp = g_att + ((size_t)b * NQ + qrow) * (NH * HDIM) + h * HDIM;
#pragma unroll
        for (int nj = 0; nj < 8; nj++) {
            float2 v = make_float2(O[nj][2 * hf] * inv, O[nj][2 * hf + 1] * inv);
            *(float2*)(outp + nj * 8 + 2 * t4) = v;
        }
    }
}

// ---------------- launch -----------------------------------------------------
extern "C" void kernel_launch(void* const* d_in, const int* in_sizes, int n_in,
                              void* d_out, int out_size)
{
    const float* q     = (const float*)d_in[0];
    const float* k     = (const float*)d_in[1];
    const float* v     = (const float*)d_in[2];
    const float* dist  = (const float*)d_in[3];
    const void*  amask = d_in[4];
    const void*  kpmq  = d_in[5];
    const void*  kpmk  = d_in[6];
    const float* Wq    = (const float*)d_in[7];
    const float* Wk    = (const float*)d_in[8];
    const float* Wv    = (const float*)d_in[9];
    const float* Wo    = (const float*)d_in[10];
    const float* ga    = (const float*)d_in[11];
    float* out = (float*)d_out;

    const int attn_smem = ATTN_SMEM_UINTS * (int)sizeof(unsigned);  // ~105.5 KB
    cudaFuncSetAttribute(attn_kernel,
                         cudaFuncAttributeMaxDynamicSharedMemorySize, attn_smem);

    detect_kernel<<<1, 256>>>((const unsigned int*)amask);

    gemm_tf32<<<dim3(8, 16), 256>>>(q, Wq, nullptr, BB * NQ,  NQ,  0, nullptr);
    gemm_tf32<<<dim3(8, 32), 256>>>(k, Wk, nullptr, BB * NKK, NKK, 1, nullptr);
    gemm_tf32<<<dim3(8, 32), 256>>>(v, Wv, nullptr, BB * NKK, NKK, 2, nullptr);

    mean_stage1<<<dim3(256, BB), 256>>>(dist, amask, kpmk);
    mean_stage2<<<BB, 256>>>(ga);
    gate_kernel<<<(BB * NQ * NKK) / (256 * 4), 256>>>(dist, amask, kpmk);

    attn_kernel<<<dim3(NQ / 128, NH, BB), 256, attn_smem>>>();

    gemm_tf32<<<dim3(8, 16), 256>>>(nullptr, Wo, out, BB * NQ, NQ, 3, kpmq);
}